// round 4
// baseline (speedup 1.0000x reference)
#include <cuda_runtime.h>
#include <cstdint>

// Problem constants (fixed shapes)
#define T_DIM 64
#define U_DIM 142
#define I_DIM 4500
#define K_TOP 10
#define ROWS_PER_WARP 2

#define NEG_BIG (-3.0e38f)

// Warp-wide top-K accumulate over 142 masked-sim values held in 5 register
// slots per lane (v = lane + 32*slot). Returns acc/(wsum+eps) on lane 0.
__device__ __forceinline__ float topk_accum(
    float m0, float m1, float m2, float m3, float m4,
    float d0, float d1, float d2, float d3, float d4,
    int lane)
{
    float wsum = 0.f, acc = 0.f;
    #pragma unroll
    for (int k = 0; k < K_TOP; ++k) {
        // local argmax (value-major; lowest slot first = lowest index on tie)
        float bv = m0; int bslot = 0;
        if (m1 > bv) { bv = m1; bslot = 1; }
        if (m2 > bv) { bv = m2; bslot = 2; }
        if (m3 > bv) { bv = m3; bslot = 3; }
        if (m4 > bv) { bv = m4; bslot = 4; }
        int bidx = lane + (bslot << 5);

        // warp argmax; tie -> smaller global index (lax.top_k stability)
        #pragma unroll
        for (int off = 16; off > 0; off >>= 1) {
            float ov = __shfl_xor_sync(0xffffffffu, bv,   off);
            int   oi = __shfl_xor_sync(0xffffffffu, bidx, off);
            if (ov > bv || (ov == bv && oi < bidx)) { bv = ov; bidx = oi; }
        }
        int wlane = bidx & 31;
        int wslot = bidx >> 5;

        float dcand = (wslot == 0) ? d0 :
                      (wslot == 1) ? d1 :
                      (wslot == 2) ? d2 :
                      (wslot == 3) ? d3 : d4;
        float dwin = __shfl_sync(0xffffffffu, dcand, wlane);

        if (lane == wlane) {
            if      (wslot == 0) m0 = NEG_BIG;
            else if (wslot == 1) m1 = NEG_BIG;
            else if (wslot == 2) m2 = NEG_BIG;
            else if (wslot == 3) m3 = NEG_BIG;
            else                 m4 = NEG_BIG;
        }
        wsum += bv;
        acc  += bv * dwin;
    }
    return acc / (wsum + 1e-8f);
}

__global__ __launch_bounds__(256)
void ucf_kernel(const float* __restrict__ qos,        // [T, U, I]
                const float* __restrict__ user_avg,   // [T, U]
                const float* __restrict__ user_sim,   // [U, U]
                const int*   __restrict__ user_id,    // [B]
                const int*   __restrict__ item_id,    // [B]
                const int*   __restrict__ time_id,    // [B]
                float*       __restrict__ out,        // [B]
                int B)
{
    const int warp = (blockIdx.x * blockDim.x + threadIdx.x) >> 5;
    const int lane = threadIdx.x & 31;

    const int r0 = warp * ROWS_PER_WARP;
    const int r1 = r0 + 1;
    if (r0 >= B) return;
    const bool have1 = (r1 < B);

    // ---- row ids ----
    const int u0 = user_id[r0], i0 = item_id[r0], t0 = time_id[r0];
    const int u1 = have1 ? user_id[r1] : u0;
    const int i1 = have1 ? item_id[r1] : i0;
    const int t1 = have1 ? time_id[r1] : t0;

    const float* qb0 = qos + (int64_t)t0 * (U_DIM * I_DIM) + i0;
    const float* qb1 = qos + (int64_t)t1 * (U_DIM * I_DIM) + i1;
    const float* ab0 = user_avg + t0 * U_DIM;
    const float* ab1 = user_avg + t1 * U_DIM;
    const float* sb0 = user_sim + u0 * U_DIM;
    const float* sb1 = user_sim + u1 * U_DIM;

    const int v0 = lane, v1 = lane + 32, v2 = lane + 64, v3 = lane + 96, v4 = lane + 128;
    const bool tail = (v4 < U_DIM);

    // ---- issue ALL scattered qos loads (both rows) up front: MLP = 10 ----
    float c00 = __ldg(qb0 + (int64_t)v0 * I_DIM);
    float c01 = __ldg(qb0 + (int64_t)v1 * I_DIM);
    float c02 = __ldg(qb0 + (int64_t)v2 * I_DIM);
    float c03 = __ldg(qb0 + (int64_t)v3 * I_DIM);
    float c04 = tail ? __ldg(qb0 + (int64_t)v4 * I_DIM) : 0.f;

    float c10 = __ldg(qb1 + (int64_t)v0 * I_DIM);
    float c11 = __ldg(qb1 + (int64_t)v1 * I_DIM);
    float c12 = __ldg(qb1 + (int64_t)v2 * I_DIM);
    float c13 = __ldg(qb1 + (int64_t)v3 * I_DIM);
    float c14 = tail ? __ldg(qb1 + (int64_t)v4 * I_DIM) : 0.f;

    // ---- row 0: sim/avg (L2-resident), convert, top-k ----
    {
        float s0 = __ldg(sb0 + v0), a0 = __ldg(ab0 + v0);
        float s1 = __ldg(sb0 + v1), a1 = __ldg(ab0 + v1);
        float s2 = __ldg(sb0 + v2), a2 = __ldg(ab0 + v2);
        float s3 = __ldg(sb0 + v3), a3 = __ldg(ab0 + v3);
        float s4 = tail ? __ldg(sb0 + v4) : 0.f;
        float a4 = tail ? __ldg(ab0 + v4) : 0.f;

        float m0 = (c00 > 0.f) ? s0 : 0.f, d0 = c00 - a0;
        float m1 = (c01 > 0.f) ? s1 : 0.f, d1 = c01 - a1;
        float m2 = (c02 > 0.f) ? s2 : 0.f, d2 = c02 - a2;
        float m3 = (c03 > 0.f) ? s3 : 0.f, d3 = c03 - a3;
        float m4 = tail ? ((c04 > 0.f) ? s4 : 0.f) : NEG_BIG;
        float d4 = c04 - a4;

        float corr = topk_accum(m0, m1, m2, m3, m4, d0, d1, d2, d3, d4, lane);
        if (lane == 0) out[r0] = __ldg(ab0 + u0) + corr;
    }

    // ---- row 1 (its qos loads have been in flight during row0's top-k) ----
    if (have1) {
        float s0 = __ldg(sb1 + v0), a0 = __ldg(ab1 + v0);
        float s1 = __ldg(sb1 + v1), a1 = __ldg(ab1 + v1);
        float s2 = __ldg(sb1 + v2), a2 = __ldg(ab1 + v2);
        float s3 = __ldg(sb1 + v3), a3 = __ldg(ab1 + v3);
        float s4 = tail ? __ldg(sb1 + v4) : 0.f;
        float a4 = tail ? __ldg(ab1 + v4) : 0.f;

        float m0 = (c10 > 0.f) ? s0 : 0.f, d0 = c10 - a0;
        float m1 = (c11 > 0.f) ? s1 : 0.f, d1 = c11 - a1;
        float m2 = (c12 > 0.f) ? s2 : 0.f, d2 = c12 - a2;
        float m3 = (c13 > 0.f) ? s3 : 0.f, d3 = c13 - a3;
        float m4 = tail ? ((c14 > 0.f) ? s4 : 0.f) : NEG_BIG;
        float d4 = c14 - a4;

        float corr = topk_accum(m0, m1, m2, m3, m4, d0, d1, d2, d3, d4, lane);
        if (lane == 0) out[r1] = __ldg(ab1 + u1) + corr;
    }
}

extern "C" void kernel_launch(void* const* d_in, const int* in_sizes, int n_in,
                              void* d_out, int out_size)
{
    const float* qos      = (const float*)d_in[0];
    const float* user_avg = (const float*)d_in[1];
    const float* user_sim = (const float*)d_in[2];
    const int*   user_id  = (const int*)  d_in[3];
    const int*   item_id  = (const int*)  d_in[4];
    const int*   time_id  = (const int*)  d_in[5];
    float* out = (float*)d_out;

    const int B = in_sizes[3];
    const int threads = 256;                      // 8 warps/block
    const int rows_per_block = (threads / 32) * ROWS_PER_WARP;  // 16
    const int blocks = (B + rows_per_block - 1) / rows_per_block;
    ucf_kernel<<<blocks, threads>>>(qos, user_avg, user_sim,
                                    user_id, item_id, time_id, out, B);
}

// round 6
// speedup vs baseline: 1.4065x; 1.4065x over previous
#include <cuda_runtime.h>
#include <cstdint>

// Problem constants (fixed shapes)
#define T_DIM 64
#define U_DIM 142
#define I_DIM 4500
#define K_TOP 10

#define KEY_ZERO 0x80000000u   // order-key of +0.0f

// monotone float -> u32 order key (increasing)
__device__ __forceinline__ unsigned fkey(float f) {
    unsigned u = __float_as_uint(f);
    return u ^ ((unsigned)((int)u >> 31) | 0x80000000u);
}

__global__ __launch_bounds__(256)
void ucf_kernel(const float* __restrict__ qos,        // [T, U, I]
                const float* __restrict__ user_avg,   // [T, U]
                const float* __restrict__ user_sim,   // [U, U]
                const int*   __restrict__ user_id,    // [B]
                const int*   __restrict__ item_id,    // [B]
                const int*   __restrict__ time_id,    // [B]
                float*       __restrict__ out,        // [B]
                int B)
{
    const int warp = (blockIdx.x * blockDim.x + threadIdx.x) >> 5;
    const int lane = threadIdx.x & 31;
    if (warp >= B) return;

    const int u = user_id[warp];
    const int i = item_id[warp];
    const int t = time_id[warp];

    const float* qbase = qos + (int64_t)t * (U_DIM * I_DIM) + i;
    const float* abase = user_avg + t * U_DIM;
    const float* sbase = user_sim + u * U_DIM;

    const int v0 = lane, v1 = lane + 32, v2 = lane + 64, v3 = lane + 96, v4 = lane + 128;
    const bool tail = (v4 < U_DIM);

    // ---- front-batch scattered qos loads (MLP=5, DRAM-bound) ----
    float c0 = __ldg(qbase + (int64_t)v0 * I_DIM);
    float c1 = __ldg(qbase + (int64_t)v1 * I_DIM);
    float c2 = __ldg(qbase + (int64_t)v2 * I_DIM);
    float c3 = __ldg(qbase + (int64_t)v3 * I_DIM);
    float c4 = tail ? __ldg(qbase + (int64_t)v4 * I_DIM) : 0.f;

    // L2-resident sim / avg rows
    float s0 = __ldg(sbase + v0), a0 = __ldg(abase + v0);
    float s1 = __ldg(sbase + v1), a1 = __ldg(abase + v1);
    float s2 = __ldg(sbase + v2), a2 = __ldg(abase + v2);
    float s3 = __ldg(sbase + v3), a3 = __ldg(abase + v3);
    float s4 = tail ? __ldg(sbase + v4) : 0.f;
    float a4 = tail ? __ldg(abase + v4) : 0.f;

    // masked-sim order keys + deviations
    unsigned k0 = fkey((c0 > 0.f) ? s0 : 0.f);
    unsigned k1 = fkey((c1 > 0.f) ? s1 : 0.f);
    unsigned k2 = fkey((c2 > 0.f) ? s2 : 0.f);
    unsigned k3 = fkey((c3 > 0.f) ? s3 : 0.f);
    unsigned k4 = tail ? fkey((c4 > 0.f) ? s4 : 0.f) : 0u;
    float d0 = c0 - a0, d1 = c1 - a1, d2 = c2 - a2, d3 = c3 - a3, d4 = c4 - a4;

    float wsum = 0.f;   // sum of selected sims (warp-uniform)
    float acc  = 0.f;   // per-lane partial of sim * (r_vs - avg_v)

    #pragma unroll
    for (int k = 0; k < K_TOP; ++k) {
        unsigned lmax = max(max(max(k0, k1), max(k2, k3)), k4);
        unsigned g = __reduce_max_sync(0xffffffffu, lmax);   // REDUX.MAX.U32
        if (g <= KEY_ZERO) break;  // remaining picks are zeros/unrated: contribute 0
        float gm = __uint_as_float(g ^ 0x80000000u);         // winner sim (>0 branch of key map)
        wsum += gm;                                          // uniform, no broadcast needed
        // winner lane accumulates its d locally; invalidate
        if      (k0 == g) { acc = fmaf(gm, d0, acc); k0 = 0u; }
        else if (k1 == g) { acc = fmaf(gm, d1, acc); k1 = 0u; }
        else if (k2 == g) { acc = fmaf(gm, d2, acc); k2 = 0u; }
        else if (k3 == g) { acc = fmaf(gm, d3, acc); k3 = 0u; }
        else if (k4 == g) { acc = fmaf(gm, d4, acc); k4 = 0u; }
    }

    // one final warp sum of acc
    #pragma unroll
    for (int off = 16; off > 0; off >>= 1)
        acc += __shfl_xor_sync(0xffffffffu, acc, off);

    if (lane == 0) {
        float avg_u = __ldg(abase + u);
        out[warp] = avg_u + acc / (wsum + 1e-8f);
    }
}

extern "C" void kernel_launch(void* const* d_in, const int* in_sizes, int n_in,
                              void* d_out, int out_size)
{
    const float* qos      = (const float*)d_in[0];
    const float* user_avg = (const float*)d_in[1];
    const float* user_sim = (const float*)d_in[2];
    const int*   user_id  = (const int*)  d_in[3];
    const int*   item_id  = (const int*)  d_in[4];
    const int*   time_id  = (const int*)  d_in[5];
    float* out = (float*)d_out;

    const int B = in_sizes[3];
    const int threads = 256;                 // 8 warps/block, 1 warp per row
    const int blocks  = (B * 32 + threads - 1) / threads;
    ucf_kernel<<<blocks, threads>>>(qos, user_avg, user_sim,
                                    user_id, item_id, time_id, out, B);
}